// round 9
// baseline (speedup 1.0000x reference)
#include <cuda_runtime.h>
#include <cstdint>
#include <cstddef>

#define T_LEN 1000
#define B_SZ  512
#define C_IN  22
#define H_SZ  64
#define TH    (T_LEN * H_SZ)  // 64000

typedef unsigned long long ull;

// xproj: ull index = (t*256 + rp)*256 + col ; lanes = (rowX, rowY) of pair rp
__device__ ull   g_xproj[(size_t)T_LEN * 256 * 256];
__device__ float g_wfcT[TH * 4];   // [(t*64+u)*4 + class] == [t*256 + j]

__device__ __forceinline__ ull pack2f(float lo, float hi) {
    ull r;
    uint32_t a = __float_as_uint(lo), b = __float_as_uint(hi);
    asm("mov.b64 %0, {%1, %2};" : "=l"(r) : "r"(a), "r"(b));
    return r;
}
__device__ __forceinline__ ull splat2(float w) {
    ull r;
    uint32_t u = __float_as_uint(w);
    asm("mov.b64 %0, {%1, %1};" : "=l"(r) : "r"(u));
    return r;
}
__device__ __forceinline__ void ffma2(ull& d, ull a, ull b) {
    asm("fma.rn.f32x2 %0, %1, %2, %3;" : "=l"(d) : "l"(a), "l"(b), "l"(d));
}
__device__ __forceinline__ void unpack2(ull v, float& lo, float& hi) {
    uint32_t ulo, uhi;
    asm("mov.b64 {%0, %1}, %2;" : "=r"(ulo), "=r"(uhi) : "l"(v));
    lo = __uint_as_float(ulo);
    hi = __uint_as_float(uhi);
}
__device__ __forceinline__ float tanh_fast(float x) {
    float y;
    asm("tanh.approx.f32 %0, %1;" : "=f"(y) : "f"(x));
    return y;
}

// ---------------------------------------------------------------------------
// Kernel A: x_proj precompute (row-pair packed, bias included) — R6 version.
// grid = (256 row-pairs, 16 t-tiles of 64), block = 256 (thread = gate col).
// ---------------------------------------------------------------------------
__global__ void __launch_bounds__(256) xproj_kernel(
    const float* __restrict__ x, const float* __restrict__ W_ih,
    const float* __restrict__ b_ih, const float* __restrict__ b_hh)
{
    __shared__ __align__(16) ull xs[C_IN][64];

    const int j  = threadIdx.x;
    const int rp = blockIdx.x;
    const int t0 = blockIdx.y * 64;
    const int tlen = (t0 + 64 <= T_LEN) ? 64 : (T_LEN - t0);

    const float* xbase = x + (size_t)(2 * rp) * C_IN * T_LEN;
    for (int idx = j; idx < 2 * C_IN * 64; idx += 256) {
        int r   = idx / (C_IN * 64);
        int rem = idx - r * (C_IN * 64);
        int c   = rem >> 6;
        int tt  = rem & 63;
        float v = (tt < tlen) ? xbase[(size_t)r * C_IN * T_LEN + c * T_LEN + t0 + tt] : 0.f;
        ((float*)&xs[c][tt])[r] = v;
    }

    ull wih2[C_IN];
#pragma unroll
    for (int c = 0; c < C_IN; c++) wih2[c] = splat2(W_ih[j * C_IN + c]);
    const ull bias2 = splat2(b_ih[j] + b_hh[j]);
    __syncthreads();

    for (int tt = 0; tt < tlen; tt++) {
        ull a = bias2;
#pragma unroll
        for (int c = 0; c < C_IN; c++) ffma2(a, wih2[c], xs[c][tt]);
        g_xproj[((size_t)(t0 + tt) * 256 + rp) * 256 + j] = a;
    }
}

// ---------------------------------------------------------------------------
// Kernel B: W_fc -> [(t*64+u)*4 + class]
// ---------------------------------------------------------------------------
__global__ void wfcT_kernel(const float* __restrict__ W_fc) {
    int i = blockIdx.x * 256 + threadIdx.x;   // i = t*64+u
    if (i < TH) {
        float4 v;
        v.x = W_fc[i];
        v.y = W_fc[TH + i];
        v.z = W_fc[2 * TH + i];
        v.w = W_fc[3 * TH + i];
        ((float4*)g_wfcT)[i] = v;
    }
}

// ---------------------------------------------------------------------------
// Kernel C: fused LSTM + FC + softmax. ONE barrier per step.
// grid = 256 CTAs (rows X=2cta, Y=2cta+1), block = 256, 2 CTAs/SM.
// Thread j: unit u=j>>2, gate gt=j&3, W-column col=64*gt+u.
// Quad-shuffle gate exchange; all threads do state update redundantly.
// ---------------------------------------------------------------------------
__global__ void __launch_bounds__(256, 2) lstm_fused(
    const float* __restrict__ W_hh, const float* __restrict__ b_fc,
    float* __restrict__ out)
{
    __shared__ __align__(16) ull hXp[2][32], hYp[2][32];  // unit-pair packed, dbl-buf
    __shared__ float red[2 * 4 * 64];
    __shared__ float logits_sh[2][4];

    const int j   = threadIdx.x;
    const int cta = blockIdx.x;       // row pair
    const int u   = j >> 2;
    const int gt  = j & 3;
    const int col = gt * H_SZ + u;

    // pack W_hh row `col` as unit-pairs (once)
    ull whhp[32];
    {
        const float4* wp = reinterpret_cast<const float4*>(W_hh + col * H_SZ);
#pragma unroll
        for (int k = 0; k < 16; k++) {
            float4 v = wp[k];
            whhp[2*k]   = pack2f(v.x, v.y);
            whhp[2*k+1] = pack2f(v.z, v.w);
        }
    }

    // nonlinearity: gt==2 (g-gate) tanh, else sigmoid = 0.5+0.5*tanh(x/2)
    const bool  is_g   = (gt == 2);
    const float nl_pre = is_g ? 1.f : 0.5f;
    const float nl_sc  = is_g ? 1.f : 0.5f;
    const float nl_off = is_g ? 0.f : 0.5f;

    if (j < 32)       hXp[0][j] = 0ull;
    else if (j < 64)  hYp[0][j - 32] = 0ull;

    float cX = 0.f, cY = 0.f;          // cell state of unit u (replicated in quad)
    float pX = 0.f, pY = 0.f;          // FC partial, class gt

    // prefetches for t=0
    const ull* xq = g_xproj + (size_t)cta * 256 + col;
    ull   xv = xq[0];
    float wf = g_wfcT[j];
    const int qbase = j & ~3;          // quad base lane (mod 32 by shfl)

    __syncthreads();

    for (int t = 0; t < T_LEN; t++) {
        const int buf = t & 1;

        // ---- gate GEMV over h (both rows): 4 chains, 32 LDS.128 ----
        ull aX0 = 0ull, aX1 = 0ull, aY0 = 0ull, aY1 = 0ull;
        const ulonglong2* hpX = reinterpret_cast<const ulonglong2*>(hXp[buf]);
        const ulonglong2* hpY = reinterpret_cast<const ulonglong2*>(hYp[buf]);
#pragma unroll
        for (int k = 0; k < 16; k++) {
            ulonglong2 hA = hpX[k];
            ulonglong2 hB = hpY[k];
            ffma2(aX0, whhp[2*k],     hA.x);
            ffma2(aY0, whhp[2*k],     hB.x);
            ffma2(aX1, whhp[2*k + 1], hA.y);
            ffma2(aY1, whhp[2*k + 1], hB.y);
        }

        // prefetch t+1 inputs (overlap the chains above)
        const int tn = (t + 1 < T_LEN) ? t + 1 : t;
        ull   xn  = xq[(size_t)tn * 65536];
        float wfn = g_wfcT[tn * 256 + j];

        // combine + nonlinearity
        float xpX, xpY, s, h2;
        unpack2(xv, xpX, xpY);
        unpack2(aX0, s, h2); float sX = s + h2;
        unpack2(aX1, s, h2); float vX = sX + (s + h2) + xpX;
        unpack2(aY0, s, h2); float sY = s + h2;
        unpack2(aY1, s, h2); float vY = sY + (s + h2) + xpY;
        float nX = fmaf(nl_sc, tanh_fast(nl_pre * vX), nl_off);
        float nY = fmaf(nl_sc, tanh_fast(nl_pre * vY), nl_off);
        ull g = pack2f(nX, nY);

        // ---- quad all-gather of {i,f,g,o} via 4 idx-shuffles ----
        ull gi = __shfl_sync(0xffffffffu, g, qbase + 0);
        ull gf = __shfl_sync(0xffffffffu, g, qbase + 1);
        ull gg = __shfl_sync(0xffffffffu, g, qbase + 2);
        ull go = __shfl_sync(0xffffffffu, g, qbase + 3);

        float iX, iY, fX, fY, gX, gY, oX, oY;
        unpack2(gi, iX, iY);
        unpack2(gf, fX, fY);
        unpack2(gg, gX, gY);
        unpack2(go, oX, oY);

        // ---- state update (redundant in quad; deterministic) ----
        cX = fmaf(fX, cX, iX * gX);
        cY = fmaf(fY, cY, iY * gY);
        float hXv = oX * tanh_fast(cX);
        float hYv = oY * tanh_fast(cY);

        // publish h(t) into the alternate buffer (one lane per quad)
        if (gt == 0) {
            ((float*)hXp[buf ^ 1])[u] = hXv;
            ((float*)hYp[buf ^ 1])[u] = hYv;
        }

        // ---- FC accumulation (class gt, unit u) ----
        pX = fmaf(hXv, wf, pX);
        pY = fmaf(hYv, wf, pY);

        xv = xn;
        wf = wfn;
        __syncthreads();   // h(t) visible for step t+1
    }

    // ---- FC reduction + softmax ----
    red[(0 * 4 + gt) * 64 + u] = pX;
    red[(1 * 4 + gt) * 64 + u] = pY;
    __syncthreads();
    if (j < 8) {
        int rr = j >> 2, nn = j & 3;
        float sum = 0.f;
#pragma unroll
        for (int k = 0; k < 64; k++) sum += red[(rr * 4 + nn) * 64 + k];
        logits_sh[rr][nn] = sum + b_fc[nn];
    }
    __syncthreads();
    if (j < 2) {
        float l0 = logits_sh[j][0], l1 = logits_sh[j][1];
        float l2 = logits_sh[j][2], l3 = logits_sh[j][3];
        float m  = fmaxf(fmaxf(l0, l1), fmaxf(l2, l3));
        float q0 = __expf(l0 - m), q1 = __expf(l1 - m);
        float q2 = __expf(l2 - m), q3 = __expf(l3 - m);
        float inv = 1.f / (q0 + q1 + q2 + q3);
        float* o = out + (2 * cta + j) * 4;
        o[0] = q0 * inv; o[1] = q1 * inv; o[2] = q2 * inv; o[3] = q3 * inv;
    }
}

// ---------------------------------------------------------------------------
extern "C" void kernel_launch(void* const* d_in, const int* in_sizes, int n_in,
                              void* d_out, int out_size) {
    const float* x    = (const float*)d_in[0];
    const float* W_ih = (const float*)d_in[1];
    const float* W_hh = (const float*)d_in[2];
    const float* b_ih = (const float*)d_in[3];
    const float* b_hh = (const float*)d_in[4];
    const float* W_fc = (const float*)d_in[5];
    const float* b_fc = (const float*)d_in[6];
    float* out = (float*)d_out;

    xproj_kernel<<<dim3(256, 16), 256>>>(x, W_ih, b_ih, b_hh);
    wfcT_kernel<<<(TH + 255) / 256, 256>>>(W_fc);
    lstm_fused<<<256, 256>>>(W_hh, b_fc, out);
}

// round 10
// speedup vs baseline: 1.6059x; 1.6059x over previous
#include <cuda_runtime.h>
#include <cstdint>
#include <cstddef>

#define T_LEN 1000
#define B_SZ  512
#define C_IN  22
#define H_SZ  64
#define TH    (T_LEN * H_SZ)  // 64000

typedef unsigned long long ull;

// xproj: ull index = (t*256 + rp)*256 + col ; lanes = (rowX, rowY) of pair rp
__device__ ull   g_xproj[(size_t)T_LEN * 256 * 256];
__device__ float g_wfcT[TH * 4];   // [(t*64+u)*4 + class] == [t*256 + (4u+gt)]

__device__ __forceinline__ ull pack2f(float lo, float hi) {
    ull r;
    uint32_t a = __float_as_uint(lo), b = __float_as_uint(hi);
    asm("mov.b64 %0, {%1, %2};" : "=l"(r) : "r"(a), "r"(b));
    return r;
}
__device__ __forceinline__ ull splat2(float w) {
    ull r;
    uint32_t u = __float_as_uint(w);
    asm("mov.b64 %0, {%1, %1};" : "=l"(r) : "r"(u));
    return r;
}
__device__ __forceinline__ void ffma2(ull& d, ull a, ull b) {
    asm("fma.rn.f32x2 %0, %1, %2, %3;" : "=l"(d) : "l"(a), "l"(b), "l"(d));
}
__device__ __forceinline__ void unpack2(ull v, float& lo, float& hi) {
    uint32_t ulo, uhi;
    asm("mov.b64 {%0, %1}, %2;" : "=r"(ulo), "=r"(uhi) : "l"(v));
    lo = __uint_as_float(ulo);
    hi = __uint_as_float(uhi);
}
__device__ __forceinline__ float tanh_fast(float x) {
    float y;
    asm("tanh.approx.f32 %0, %1;" : "=f"(y) : "f"(x));
    return y;
}

// ---------------------------------------------------------------------------
// Kernel A: x_proj precompute (row-pair packed, bias included).
// grid = (256 row-pairs, 8 t-tiles of 128), block = 256 (thread = gate col).
// Inner loop processes 2 timesteps per iteration: 11 broadcast LDS.128 per tt.
// ---------------------------------------------------------------------------
__global__ void __launch_bounds__(256) xproj_kernel(
    const float* __restrict__ x, const float* __restrict__ W_ih,
    const float* __restrict__ b_ih, const float* __restrict__ b_hh)
{
    __shared__ __align__(16) ull xs[C_IN][128];   // [ch][tt], lanes = row pair

    const int j  = threadIdx.x;
    const int rp = blockIdx.x;
    const int t0 = blockIdx.y * 128;
    const int tlen = (t0 + 128 <= T_LEN) ? 128 : (T_LEN - t0);   // 128 or 104 (even)

    const float* xbase = x + (size_t)(2 * rp) * C_IN * T_LEN;
    for (int idx = j; idx < 2 * C_IN * 128; idx += 256) {
        int r   = idx / (C_IN * 128);
        int rem = idx - r * (C_IN * 128);
        int c   = rem >> 7;
        int tt  = rem & 127;
        float v = (tt < tlen) ? xbase[(size_t)r * C_IN * T_LEN + c * T_LEN + t0 + tt] : 0.f;
        ((float*)&xs[c][tt])[r] = v;
    }

    ull wih2[C_IN];
#pragma unroll
    for (int c = 0; c < C_IN; c++) wih2[c] = splat2(W_ih[j * C_IN + c]);
    const ull bias2 = splat2(b_ih[j] + b_hh[j]);
    __syncthreads();

    for (int i = 0; i < tlen; i += 2) {
        ull a0 = bias2, a1 = bias2;
#pragma unroll
        for (int c = 0; c < C_IN; c++) {
            ulonglong2 xc = *(const ulonglong2*)&xs[c][i];   // tt i, i+1 (broadcast)
            ffma2(a0, wih2[c], xc.x);
            ffma2(a1, wih2[c], xc.y);
        }
        size_t base = ((size_t)(t0 + i) * 256 + rp) * 256 + j;
        g_xproj[base]         = a0;
        g_xproj[base + 65536] = a1;   // next t: +256*256
    }
}

// ---------------------------------------------------------------------------
// Kernel B: W_fc -> [(t*64+u)*4 + class]
// ---------------------------------------------------------------------------
__global__ void wfcT_kernel(const float* __restrict__ W_fc) {
    int i = blockIdx.x * 256 + threadIdx.x;   // i = t*64+u
    if (i < TH) {
        float4 v;
        v.x = W_fc[i];
        v.y = W_fc[TH + i];
        v.z = W_fc[2 * TH + i];
        v.w = W_fc[3 * TH + i];
        ((float4*)g_wfcT)[i] = v;
    }
}

// ---------------------------------------------------------------------------
// Kernel C: fused LSTM + FC + softmax. ONE __syncthreads per step.
// grid = 256 CTAs (rows X=2cta, Y=2cta+1), block = 256, 2 CTAs/SM.
// Thread j: unit u=j>>2, gate gt=j&3, W-column col=64*gt+u.
// Gate exchange is WARP-LOCAL: STS.64 -> __syncwarp -> 2x LDS.128 of the quad.
// ---------------------------------------------------------------------------
__global__ void __launch_bounds__(256, 2) lstm_fused(
    const float* __restrict__ W_hh, const float* __restrict__ b_fc,
    float* __restrict__ out)
{
    __shared__ __align__(16) ull hXp[2][32], hYp[2][32];  // h unit-pair packed, dbl-buf
    __shared__ __align__(16) ull g2[256];                 // gates (rowX,rowY) per col idx j
    __shared__ float red[2 * 4 * 64];
    __shared__ float logits_sh[2][4];

    const int j   = threadIdx.x;
    const int cta = blockIdx.x;       // row pair
    const int u   = j >> 2;
    const int gt  = j & 3;
    const int col = gt * H_SZ + u;

    // pack W_hh row `col` as unit-pairs (once)
    ull whhp[32];
    {
        const float4* wp = reinterpret_cast<const float4*>(W_hh + col * H_SZ);
#pragma unroll
        for (int k = 0; k < 16; k++) {
            float4 v = wp[k];
            whhp[2*k]   = pack2f(v.x, v.y);
            whhp[2*k+1] = pack2f(v.z, v.w);
        }
    }

    // nonlinearity: gt==2 (g-gate) tanh, else sigmoid = 0.5+0.5*tanh(x/2)
    const bool  is_g   = (gt == 2);
    const float nl_pre = is_g ? 1.f : 0.5f;
    const float nl_sc  = is_g ? 1.f : 0.5f;
    const float nl_off = is_g ? 0.f : 0.5f;

    if (j < 32)       hXp[0][j] = 0ull;
    else if (j < 64)  hYp[0][j - 32] = 0ull;

    float cX = 0.f, cY = 0.f;          // cell state of unit u (replicated in quad)
    float pX = 0.f, pY = 0.f;          // FC partial, class gt

    // prefetches for t=0
    const ull* xq = g_xproj + (size_t)cta * 256 + col;
    ull   xv = xq[0];
    float wf = g_wfcT[j];              // wfcT[t*256 + 4u+gt] with j = 4u+gt

    __syncthreads();

    for (int t = 0; t < T_LEN; t++) {
        const int buf = t & 1;

        // ---- gate GEMV over h (both rows): 4 chains, 32 broadcast LDS.128 ----
        ull aX0 = 0ull, aX1 = 0ull, aY0 = 0ull, aY1 = 0ull;
        const ulonglong2* hpX = reinterpret_cast<const ulonglong2*>(hXp[buf]);
        const ulonglong2* hpY = reinterpret_cast<const ulonglong2*>(hYp[buf]);
#pragma unroll
        for (int k = 0; k < 16; k++) {
            ulonglong2 hA = hpX[k];
            ulonglong2 hB = hpY[k];
            ffma2(aX0, whhp[2*k],     hA.x);
            ffma2(aY0, whhp[2*k],     hB.x);
            ffma2(aX1, whhp[2*k + 1], hA.y);
            ffma2(aY1, whhp[2*k + 1], hB.y);
        }

        // prefetch t+1 inputs (overlap the chains above)
        const int tn = (t + 1 < T_LEN) ? t + 1 : t;
        ull   xn  = xq[(size_t)tn * 65536];
        float wfn = g_wfcT[tn * 256 + j];

        // combine + nonlinearity (2 per thread)
        float xpX, xpY, s, h2;
        unpack2(xv, xpX, xpY);
        unpack2(aX0, s, h2); float sX = s + h2;
        unpack2(aX1, s, h2); float vX = sX + (s + h2) + xpX;
        unpack2(aY0, s, h2); float sY = s + h2;
        unpack2(aY1, s, h2); float vY = sY + (s + h2) + xpY;
        float nX = fmaf(nl_sc, tanh_fast(nl_pre * vX), nl_off);
        float nY = fmaf(nl_sc, tanh_fast(nl_pre * vY), nl_off);
        g2[j] = pack2f(nX, nY);
        __syncwarp();      // quad producers/consumers are in the same warp

        // ---- read the quad {i,f,g,o} of unit u: 2x LDS.128, conflict-free ----
        const ulonglong2* gq = reinterpret_cast<const ulonglong2*>(&g2[u << 2]);
        ulonglong2 q0 = gq[0], q1 = gq[1];
        float iX, iY, fX, fY, gX, gY, oX, oY;
        unpack2(q0.x, iX, iY);
        unpack2(q0.y, fX, fY);
        unpack2(q1.x, gX, gY);
        unpack2(q1.y, oX, oY);

        // ---- state update (redundant in quad; deterministic) ----
        cX = fmaf(fX, cX, iX * gX);
        cY = fmaf(fY, cY, iY * gY);
        float hXv = oX * tanh_fast(cX);
        float hYv = oY * tanh_fast(cY);

        // publish h(t) into the alternate buffer (one lane per quad)
        if (gt == 0) {
            ((float*)hXp[buf ^ 1])[u] = hXv;
            ((float*)hYp[buf ^ 1])[u] = hYv;
        }

        // ---- FC accumulation (class gt, unit u) ----
        pX = fmaf(hXv, wf, pX);
        pY = fmaf(hYv, wf, pY);

        xv = xn;
        wf = wfn;
        __syncthreads();   // h(t) visible for step t+1  (ONLY full barrier)
    }

    // ---- FC reduction + softmax ----
    red[(0 * 4 + gt) * 64 + u] = pX;
    red[(1 * 4 + gt) * 64 + u] = pY;
    __syncthreads();
    if (j < 8) {
        int rr = j >> 2, nn = j & 3;
        float sum = 0.f;
#pragma unroll
        for (int k = 0; k < 64; k++) sum += red[(rr * 4 + nn) * 64 + k];
        logits_sh[rr][nn] = sum + b_fc[nn];
    }
    __syncthreads();
    if (j < 2) {
        float l0 = logits_sh[j][0], l1 = logits_sh[j][1];
        float l2 = logits_sh[j][2], l3 = logits_sh[j][3];
        float m  = fmaxf(fmaxf(l0, l1), fmaxf(l2, l3));
        float q0 = __expf(l0 - m), q1 = __expf(l1 - m);
        float q2 = __expf(l2 - m), q3 = __expf(l3 - m);
        float inv = 1.f / (q0 + q1 + q2 + q3);
        float* o = out + (2 * cta + j) * 4;
        o[0] = q0 * inv; o[1] = q1 * inv; o[2] = q2 * inv; o[3] = q3 * inv;
    }
}

// ---------------------------------------------------------------------------
extern "C" void kernel_launch(void* const* d_in, const int* in_sizes, int n_in,
                              void* d_out, int out_size) {
    const float* x    = (const float*)d_in[0];
    const float* W_ih = (const float*)d_in[1];
    const float* W_hh = (const float*)d_in[2];
    const float* b_ih = (const float*)d_in[3];
    const float* b_hh = (const float*)d_in[4];
    const float* W_fc = (const float*)d_in[5];
    const float* b_fc = (const float*)d_in[6];
    float* out = (float*)d_out;

    xproj_kernel<<<dim3(256, 8), 256>>>(x, W_ih, b_ih, b_hh);
    wfcT_kernel<<<(TH + 255) / 256, 256>>>(W_fc);
    lstm_fused<<<256, 256>>>(W_hh, b_fc, out);
}

// round 11
// speedup vs baseline: 1.6530x; 1.0293x over previous
#include <cuda_runtime.h>
#include <cstdint>
#include <cstddef>

#define T_LEN 1000
#define B_SZ  512
#define C_IN  22
#define H_SZ  64
#define TH    (T_LEN * H_SZ)  // 64000

typedef unsigned long long ull;

// xproj: ull index = (t*256 + rp)*256 + j, where slot j holds gate column
// c(j) = (j&3)*64 + (j>>2)  (pre-permuted for the main kernel's quad mapping).
// lanes = (rowX, rowY) of pair rp. Bias included.
__device__ ull   g_xproj[(size_t)T_LEN * 256 * 256];
__device__ float g_wfcT[TH * 4];   // [(t*64+u)*4 + class] == [t*256 + (4u+gt)]

__device__ __forceinline__ ull pack2f(float lo, float hi) {
    ull r;
    uint32_t a = __float_as_uint(lo), b = __float_as_uint(hi);
    asm("mov.b64 %0, {%1, %2};" : "=l"(r) : "r"(a), "r"(b));
    return r;
}
__device__ __forceinline__ ull splat2(float w) {
    ull r;
    uint32_t u = __float_as_uint(w);
    asm("mov.b64 %0, {%1, %1};" : "=l"(r) : "r"(u));
    return r;
}
__device__ __forceinline__ void ffma2(ull& d, ull a, ull b) {
    asm("fma.rn.f32x2 %0, %1, %2, %3;" : "=l"(d) : "l"(a), "l"(b), "l"(d));
}
__device__ __forceinline__ void unpack2(ull v, float& lo, float& hi) {
    uint32_t ulo, uhi;
    asm("mov.b64 {%0, %1}, %2;" : "=r"(ulo), "=r"(uhi) : "l"(v));
    lo = __uint_as_float(ulo);
    hi = __uint_as_float(uhi);
}
__device__ __forceinline__ float tanh_fast(float x) {
    float y;
    asm("tanh.approx.f32 %0, %1;" : "=f"(y) : "f"(x));
    return y;
}

// ---------------------------------------------------------------------------
// Kernel A: x_proj precompute (row-pair packed, bias included).
// grid = (256 row-pairs, 8 t-tiles of 128), block = 256.
// Thread j computes gate column c(j) = (j&3)*64 + (j>>2) and stores into
// slot j -> coalesced stores AND coalesced reads in the main kernel.
// ---------------------------------------------------------------------------
__global__ void __launch_bounds__(256) xproj_kernel(
    const float* __restrict__ x, const float* __restrict__ W_ih,
    const float* __restrict__ b_ih, const float* __restrict__ b_hh)
{
    __shared__ __align__(16) ull xs[C_IN][128];   // [ch][tt], lanes = row pair

    const int j   = threadIdx.x;
    const int col = (j & 3) * H_SZ + (j >> 2);    // quad-permuted gate column
    const int rp  = blockIdx.x;
    const int t0  = blockIdx.y * 128;
    const int tlen = (t0 + 128 <= T_LEN) ? 128 : (T_LEN - t0);   // 128 or 104

    const float* xbase = x + (size_t)(2 * rp) * C_IN * T_LEN;
    for (int idx = j; idx < 2 * C_IN * 128; idx += 256) {
        int r   = idx / (C_IN * 128);
        int rem = idx - r * (C_IN * 128);
        int c   = rem >> 7;
        int tt  = rem & 127;
        float v = (tt < tlen) ? xbase[(size_t)r * C_IN * T_LEN + c * T_LEN + t0 + tt] : 0.f;
        ((float*)&xs[c][tt])[r] = v;
    }

    ull wih2[C_IN];
#pragma unroll
    for (int c = 0; c < C_IN; c++) wih2[c] = splat2(W_ih[col * C_IN + c]);
    const ull bias2 = splat2(b_ih[col] + b_hh[col]);
    __syncthreads();

    for (int i = 0; i < tlen; i += 2) {
        ull a0 = bias2, a1 = bias2;
#pragma unroll
        for (int c = 0; c < C_IN; c++) {
            ulonglong2 xc = *(const ulonglong2*)&xs[c][i];   // tt i, i+1 (broadcast)
            ffma2(a0, wih2[c], xc.x);
            ffma2(a1, wih2[c], xc.y);
        }
        size_t base = ((size_t)(t0 + i) * 256 + rp) * 256 + j;
        g_xproj[base]         = a0;
        g_xproj[base + 65536] = a1;   // next t: +256*256
    }
}

// ---------------------------------------------------------------------------
// Kernel B: W_fc -> [(t*64+u)*4 + class]
// ---------------------------------------------------------------------------
__global__ void wfcT_kernel(const float* __restrict__ W_fc) {
    int i = blockIdx.x * 256 + threadIdx.x;   // i = t*64+u
    if (i < TH) {
        float4 v;
        v.x = W_fc[i];
        v.y = W_fc[TH + i];
        v.z = W_fc[2 * TH + i];
        v.w = W_fc[3 * TH + i];
        ((float4*)g_wfcT)[i] = v;
    }
}

// ---------------------------------------------------------------------------
// Kernel C: fused LSTM + FC + softmax. ONE __syncthreads per step.
// grid = 256 CTAs (rows X=2cta, Y=2cta+1), block = 256, 2 CTAs/SM.
// Thread j: unit u=j>>2, gate gt=j&3, W-column col=64*gt+u.
// Gate exchange is WARP-LOCAL: STS.64 -> __syncwarp -> 2x LDS.128 of the quad.
// xproj reads xq[j]: fully coalesced (array pre-permuted by kernel A).
// ---------------------------------------------------------------------------
__global__ void __launch_bounds__(256, 2) lstm_fused(
    const float* __restrict__ W_hh, const float* __restrict__ b_fc,
    float* __restrict__ out)
{
    __shared__ __align__(16) ull hXp[2][32], hYp[2][32];  // h unit-pair packed, dbl-buf
    __shared__ __align__(16) ull g2[256];                 // gates (rowX,rowY)
    __shared__ float red[2 * 4 * 64];
    __shared__ float logits_sh[2][4];

    const int j   = threadIdx.x;
    const int cta = blockIdx.x;       // row pair
    const int u   = j >> 2;
    const int gt  = j & 3;
    const int col = gt * H_SZ + u;

    // pack W_hh row `col` as unit-pairs (once)
    ull whhp[32];
    {
        const float4* wp = reinterpret_cast<const float4*>(W_hh + col * H_SZ);
#pragma unroll
        for (int k = 0; k < 16; k++) {
            float4 v = wp[k];
            whhp[2*k]   = pack2f(v.x, v.y);
            whhp[2*k+1] = pack2f(v.z, v.w);
        }
    }

    // nonlinearity: gt==2 (g-gate) tanh, else sigmoid = 0.5+0.5*tanh(x/2)
    const bool  is_g   = (gt == 2);
    const float nl_pre = is_g ? 1.f : 0.5f;
    const float nl_sc  = is_g ? 1.f : 0.5f;
    const float nl_off = is_g ? 0.f : 0.5f;

    if (j < 32)       hXp[0][j] = 0ull;
    else if (j < 64)  hYp[0][j - 32] = 0ull;

    float cX = 0.f, cY = 0.f;          // cell state of unit u (replicated in quad)
    float pX = 0.f, pY = 0.f;          // FC partial, class gt

    // prefetches for t=0 — xq[j] is coalesced (pre-permuted layout)
    const ull* xq = g_xproj + (size_t)cta * 256 + j;
    ull   xv = xq[0];
    float wf = g_wfcT[j];

    __syncthreads();

    for (int t = 0; t < T_LEN; t++) {
        const int buf = t & 1;

        // ---- gate GEMV over h (both rows): 4 chains, 32 broadcast LDS.128 ----
        ull aX0 = 0ull, aX1 = 0ull, aY0 = 0ull, aY1 = 0ull;
        const ulonglong2* hpX = reinterpret_cast<const ulonglong2*>(hXp[buf]);
        const ulonglong2* hpY = reinterpret_cast<const ulonglong2*>(hYp[buf]);
#pragma unroll
        for (int k = 0; k < 16; k++) {
            ulonglong2 hA = hpX[k];
            ulonglong2 hB = hpY[k];
            ffma2(aX0, whhp[2*k],     hA.x);
            ffma2(aY0, whhp[2*k],     hB.x);
            ffma2(aX1, whhp[2*k + 1], hA.y);
            ffma2(aY1, whhp[2*k + 1], hB.y);
        }

        // prefetch t+1 inputs (overlap the chains above)
        const int tn = (t + 1 < T_LEN) ? t + 1 : t;
        ull   xn  = xq[(size_t)tn * 65536];
        float wfn = g_wfcT[tn * 256 + j];

        // combine + nonlinearity (2 per thread)
        float xpX, xpY, s, h2;
        unpack2(xv, xpX, xpY);
        unpack2(aX0, s, h2); float sX = s + h2;
        unpack2(aX1, s, h2); float vX = sX + (s + h2) + xpX;
        unpack2(aY0, s, h2); float sY = s + h2;
        unpack2(aY1, s, h2); float vY = sY + (s + h2) + xpY;
        float nX = fmaf(nl_sc, tanh_fast(nl_pre * vX), nl_off);
        float nY = fmaf(nl_sc, tanh_fast(nl_pre * vY), nl_off);
        g2[j] = pack2f(nX, nY);
        __syncwarp();      // quad producers/consumers are in the same warp

        // ---- read the quad {i,f,g,o} of unit u: 2x LDS.128, conflict-free ----
        const ulonglong2* gq = reinterpret_cast<const ulonglong2*>(&g2[u << 2]);
        ulonglong2 q0 = gq[0], q1 = gq[1];
        float iX, iY, fX, fY, gX, gY, oX, oY;
        unpack2(q0.x, iX, iY);
        unpack2(q0.y, fX, fY);
        unpack2(q1.x, gX, gY);
        unpack2(q1.y, oX, oY);

        // ---- state update (redundant in quad; deterministic) ----
        cX = fmaf(fX, cX, iX * gX);
        cY = fmaf(fY, cY, iY * gY);
        float hXv = oX * tanh_fast(cX);
        float hYv = oY * tanh_fast(cY);

        // publish h(t) into the alternate buffer (one lane per quad)
        if (gt == 0) {
            ((float*)hXp[buf ^ 1])[u] = hXv;
            ((float*)hYp[buf ^ 1])[u] = hYv;
        }

        // ---- FC accumulation (class gt, unit u) ----
        pX = fmaf(hXv, wf, pX);
        pY = fmaf(hYv, wf, pY);

        xv = xn;
        wf = wfn;
        __syncthreads();   // h(t) visible for step t+1  (ONLY full barrier)
    }

    // ---- FC reduction + softmax ----
    red[(0 * 4 + gt) * 64 + u] = pX;
    red[(1 * 4 + gt) * 64 + u] = pY;
    __syncthreads();
    if (j < 8) {
        int rr = j >> 2, nn = j & 3;
        float sum = 0.f;
#pragma unroll
        for (int k = 0; k < 64; k++) sum += red[(rr * 4 + nn) * 64 + k];
        logits_sh[rr][nn] = sum + b_fc[nn];
    }
    __syncthreads();
    if (j < 2) {
        float l0 = logits_sh[j][0], l1 = logits_sh[j][1];
        float l2 = logits_sh[j][2], l3 = logits_sh[j][3];
        float m  = fmaxf(fmaxf(l0, l1), fmaxf(l2, l3));
        float q0 = __expf(l0 - m), q1 = __expf(l1 - m);
        float q2 = __expf(l2 - m), q3 = __expf(l3 - m);
        float inv = 1.f / (q0 + q1 + q2 + q3);
        float* o = out + (2 * cta + j) * 4;
        o[0] = q0 * inv; o[1] = q1 * inv; o[2] = q2 * inv; o[3] = q3 * inv;
    }
}

// ---------------------------------------------------------------------------
extern "C" void kernel_launch(void* const* d_in, const int* in_sizes, int n_in,
                              void* d_out, int out_size) {
    const float* x    = (const float*)d_in[0];
    const float* W_ih = (const float*)d_in[1];
    const float* W_hh = (const float*)d_in[2];
    const float* b_ih = (const float*)d_in[3];
    const float* b_hh = (const float*)d_in[4];
    const float* W_fc = (const float*)d_in[5];
    const float* b_fc = (const float*)d_in[6];
    float* out = (float*)d_out;

    xproj_kernel<<<dim3(256, 8), 256>>>(x, W_ih, b_ih, b_hh);
    wfcT_kernel<<<(TH + 255) / 256, 256>>>(W_fc);
    lstm_fused<<<256, 256>>>(W_hh, b_fc, out);
}